// round 9
// baseline (speedup 1.0000x reference)
#include <cuda_runtime.h>
#include <cuda_fp16.h>
#include <math.h>
#include <stdint.h>

// ===========================================================================
// Problem constants
// ===========================================================================
#define B_ROWS 8192
#define P_ROWS 4096
#define D_DIM  512
#define NCHUNK (P_ROWS / 128)     // 32 column chunks of 128 protos

#define BM 128
#define BN 128
#define KITERS 16                  // 32-k stages
#define NPIPE 4                    // A pipeline depth
#define A_STAGE_BYTES 8192         // 128 rows x 64B (32-k of A_hi), SW64 swizzle
#define OFF_PSQ  0                 // 128 floats
#define OFF_PLAB 512               // 128 ints
#define OFF_STAGE 1024
#define CPITCH 132                 // epilogue C smem pitch (floats)
#define EPI_BYTES (128 * CPITCH * 4)                     // 67584
#define SMEM_TOTAL (OFF_STAGE + EPI_BYTES)               // 68608 -> 2 CTAs/SM

#define NTK (D_DIM / 16)           // 32 k16 tiles
#define NTP (P_ROWS / 16)          // 256 n16 (tile-pair) blocks

// ===========================================================================
// Scratch (allocation-free)
// ===========================================================================
__device__ __half g_Ahi[B_ROWS * D_DIM];
// B in mma fragment order: [tk (32)][tp (256)][lane (32)] x uint4
// uint4 = {tile 2tp: reg0, reg1, tile 2tp+1: reg0, reg1}
__device__ uint4 g_Bfrag[NTK * NTP * 32];
__device__ float g_fsq[B_ROWS];
__device__ float g_psq[P_ROWS];
__device__ float g_pmd[NCHUNK * B_ROWS];
__device__ float g_psd[NCHUNK * B_ROWS];
__device__ float g_pmn[NCHUNK * B_ROWS];
__device__ float g_psn[NCHUNK * B_ROWS];

// ===========================================================================
// PTX helpers (base sm_103: cp.async, ldmatrix, mma.sync)
// ===========================================================================
__device__ __forceinline__ uint32_t smem_u32(const void* p) {
    uint32_t a;
    asm("{ .reg .u64 t; cvta.to.shared.u64 t, %1; cvt.u32.u64 %0, t; }" : "=r"(a) : "l"(p));
    return a;
}
__device__ __forceinline__ void cp16(uint32_t dst, const void* src) {
    asm volatile("cp.async.cg.shared.global [%0], [%1], 16;" :: "r"(dst), "l"(src));
}
#define CP_COMMIT() asm volatile("cp.async.commit_group;" ::: "memory")
#define CP_WAIT(n)  asm volatile("cp.async.wait_group %0;" :: "n"(n) : "memory")

#define LDSM_X4(r0, r1, r2, r3, a)                                              \
    asm volatile("ldmatrix.sync.aligned.m8n8.x4.shared.b16 {%0,%1,%2,%3}, [%4];" \
        : "=r"(r0), "=r"(r1), "=r"(r2), "=r"(r3) : "r"(a))

#define MMA16816(c, a, b0, b1)                                                  \
    asm volatile("mma.sync.aligned.m16n8k16.row.col.f32.f16.f16.f32 "           \
        "{%0,%1,%2,%3}, {%4,%5,%6,%7}, {%8,%9}, {%0,%1,%2,%3};"                 \
        : "+f"((c)[0]), "+f"((c)[1]), "+f"((c)[2]), "+f"((c)[3])                \
        : "r"((a)[0]), "r"((a)[1]), "r"((a)[2]), "r"((a)[3]),                   \
          "r"(b0), "r"(b1))

// ===========================================================================
// Kernel 1: fp16 quantize + squared norms OF THE QUANTIZED vectors.
// A: row-major g_Ahi. B: fragment-order g_Bfrag (m16n8k16 B operand layout:
// lane = n'*4 + (k'%8)/2, reg = (k%16)/8, halves = (k, k+1)).
// One warp per row.
// ===========================================================================
__global__ void prep_kernel(const float* __restrict__ feat,
                            const float* __restrict__ proto) {
    int warp = (blockIdx.x * blockDim.x + threadIdx.x) >> 5;
    int lane = threadIdx.x & 31;
    if (warp >= B_ROWS + P_ROWS) return;
    bool isA = warp < B_ROWS;
    int row = isA ? warp : warp - B_ROWS;
    const float* src = (isA ? feat : proto) + (size_t)row * D_DIM;

    float s = 0.f;
    if (isA) {
        __half* dh = g_Ahi + (size_t)row * D_DIM;
#pragma unroll
        for (int t = 0; t < 4; t++) {
            int k = t * 128 + lane * 4;
            float4 v = *(const float4*)(src + k);
            __align__(8) __half h[4];
            float x[4] = {v.x, v.y, v.z, v.w};
#pragma unroll
            for (int j = 0; j < 4; j++) {
                h[j] = __float2half_rn(x[j]);
                float hq = __half2float(h[j]);
                s = fmaf(hq, hq, s);
            }
            *(uint2*)(dh + k) = *(uint2*)h;
        }
    } else {
        uint32_t* dst = (uint32_t*)g_Bfrag;
        int pr = row & 7;            // n' within n8 tile
        int tp = row >> 4;           // tile-pair index
        int sub = (row >> 3) & 1;    // which tile of the pair
#pragma unroll
        for (int t = 0; t < 8; t++) {
            int k = t * 64 + lane * 2;
            float2 v = *(const float2*)(src + k);
            __half h0 = __float2half_rn(v.x);
            __half h1 = __float2half_rn(v.y);
            float q0 = __half2float(h0), q1 = __half2float(h1);
            s = fmaf(q0, q0, fmaf(q1, q1, s));
            uint32_t pack = (uint32_t)__half_as_ushort(h0)
                          | ((uint32_t)__half_as_ushort(h1) << 16);
            uint32_t idx = (uint32_t)((((k >> 4) * NTP + tp) * 32
                          + pr * 4 + ((k & 7) >> 1)) * 4
                          + sub * 2 + ((k >> 3) & 1));
            dst[idx] = pack;
        }
    }
#pragma unroll
    for (int m = 16; m; m >>= 1) s += __shfl_xor_sync(0xffffffffu, s, m);
    if (lane == 0) {
        if (isA) g_fsq[row] = s; else g_psq[row] = s;
    }
}

// ===========================================================================
// Kernel 2: 1-term fp16 mma.sync GEMM. A via cp.async+ldmatrix (smem),
// B fed DIRECTLY from L2 in fragment order (no smem, no B-LDSM).
// grid = (32 n-chunks, 64 m-tiles), 256 threads = 2(m) x 4(n) warps.
// ===========================================================================
__global__ __launch_bounds__(256, 2) void dce_mma_kernel(
    const int* __restrict__ label, const int* __restrict__ plab) {
    extern __shared__ __align__(1024) char smem[];
    float* psq_s = (float*)(smem + OFF_PSQ);
    int* plab_s = (int*)(smem + OFF_PLAB);
    char* stages = smem + OFF_STAGE;
    const uint32_t sb = smem_u32(stages);

    const int tid = threadIdx.x;
    const int lane = tid & 31;
    const int wid = tid >> 5;
    const int wm = wid >> 2;       // 0..1
    const int wn = wid & 3;        // 0..3
    const int m0 = blockIdx.y * BM;
    const int n0 = blockIdx.x * BN;
    const int tp0 = (n0 >> 4) + wn * 2;   // this warp's first tile-pair

    if (tid < 128) {
        psq_s[tid] = g_psq[n0 + tid];
        plab_s[tid] = plab[n0 + tid];
    }

    float acc[4][4][4];
#pragma unroll
    for (int i = 0; i < 4; i++)
#pragma unroll
        for (int j = 0; j < 4; j++)
#pragma unroll
            for (int q = 0; q < 4; q++) acc[i][j][q] = 0.f;

    // --- A stage loader: 2 x cp.async(16B) per thread (512 chunks) ---
    auto issue_stage = [&](int s) {
        uint32_t base = sb + (s & (NPIPE - 1)) * A_STAGE_BYTES;
        int k0 = s * 32;
#pragma unroll
        for (int j = 0; j < 2; j++) {
            int idx = tid + j * 256;
            int r = idx >> 2;
            int c = idx & 3;
            uint32_t so = (uint32_t)(r * 64 + ((c ^ ((r >> 1) & 3)) << 4));
            cp16(base + so, g_Ahi + (size_t)(m0 + r) * D_DIM + k0 + c * 8);
        }
        CP_COMMIT();
    };

    issue_stage(0);
    issue_stage(1);
    issue_stage(2);

    const uint4* __restrict__ Bf = g_Bfrag;

    for (int s = 0; s < KITERS; s++) {
        CP_WAIT(2);                // A stage s landed
        __syncthreads();           // all warps done reading stage s-1
        if (s + 3 < KITERS) issue_stage(s + 3);

        uint32_t base = sb + (s & (NPIPE - 1)) * A_STAGE_BYTES;

        // Hoist B fragment loads for both k16 slices (L2/L1 hits; latency
        // covered by the A-LDSM + MMA stream and co-resident warps).
        int tk0 = s * 2;
        uint4 b[2][2];
#pragma unroll
        for (int ks = 0; ks < 2; ks++) {
            b[ks][0] = Bf[((size_t)(tk0 + ks) * NTP + tp0) * 32 + lane];
            b[ks][1] = Bf[((size_t)(tk0 + ks) * NTP + tp0 + 1) * 32 + lane];
        }

#pragma unroll
        for (int ks = 0; ks < 2; ks++) {
#pragma unroll
            for (int mt = 0; mt < 4; mt++) {
                uint32_t Ah[4];
                int row = wm * 64 + mt * 16 + (lane & 15);
                int ch = ks * 2 + (lane >> 4);
                uint32_t ah = base + row * 64 + ((ch ^ ((row >> 1) & 3)) << 4);
                LDSM_X4(Ah[0], Ah[1], Ah[2], Ah[3], ah);
                MMA16816(acc[mt][0], Ah, b[ks][0].x, b[ks][0].y);
                MMA16816(acc[mt][1], Ah, b[ks][0].z, b[ks][0].w);
                MMA16816(acc[mt][2], Ah, b[ks][1].x, b[ks][1].y);
                MMA16816(acc[mt][3], Ah, b[ks][1].z, b[ks][1].w);
            }
        }
    }

    CP_WAIT(0);
    __syncthreads();

    // --- dump accumulators to SMEM (reuse stage memory) ---
    float* Cs = (float*)stages;
#pragma unroll
    for (int mt = 0; mt < 4; mt++)
#pragma unroll
        for (int nt = 0; nt < 4; nt++) {
            int r = wm * 64 + mt * 16 + (lane >> 2);
            int c = wn * 32 + nt * 8 + ((lane & 3) << 1);
            Cs[r * CPITCH + c] = acc[mt][nt][0];
            Cs[r * CPITCH + c + 1] = acc[mt][nt][1];
            Cs[(r + 8) * CPITCH + c] = acc[mt][nt][2];
            Cs[(r + 8) * CPITCH + c + 1] = acc[mt][nt][3];
        }
    __syncthreads();

    // --- per-thread dual online LSE over 64 cols, pair-merge, write partials
    int row = tid >> 1;
    int c0 = (tid & 1) * 64;
    float fsq = g_fsq[m0 + row];
    int lab = label[m0 + row];
    float md = -INFINITY, mn = -INFINITY;
#pragma unroll 4
    for (int j = 0; j < 64; j++) {
        int col = c0 + j;
        float dot = Cs[row * CPITCH + col];
        float d2 = fmaxf(fsq + psq_s[col] - 2.0f * dot, 0.0f);
        float lg = -d2;
        Cs[row * CPITCH + col] = lg;
        md = fmaxf(md, lg);
        if (plab_s[col] == lab) mn = fmaxf(mn, lg);
    }
    float sd = 0.f, sn = 0.f;
#pragma unroll 4
    for (int j = 0; j < 64; j++) {
        int col = c0 + j;
        float lg = Cs[row * CPITCH + col];
        sd += __expf(lg - md);
        if (plab_s[col] == lab) sn += __expf(lg - mn);
    }
    // merge with partner thread (tid ^ 1, same warp)
    float md2 = __shfl_xor_sync(0xffffffffu, md, 1);
    float sd2 = __shfl_xor_sync(0xffffffffu, sd, 1);
    float mn2 = __shfl_xor_sync(0xffffffffu, mn, 1);
    float sn2 = __shfl_xor_sync(0xffffffffu, sn, 1);
    float M = fmaxf(md, md2);
    float SD = sd * __expf(md - M) + sd2 * __expf(md2 - M);
    float Mn = fmaxf(mn, mn2);
    float f0 = (mn == -INFINITY) ? 0.f : __expf(mn - Mn);
    float f1 = (mn2 == -INFINITY) ? 0.f : __expf(mn2 - Mn);
    float SN = sn * f0 + sn2 * f1;
    if ((tid & 1) == 0) {
        size_t o = (size_t)blockIdx.x * B_ROWS + m0 + row;
        g_pmd[o] = M;
        g_psd[o] = SD;
        g_pmn[o] = Mn;
        g_psn[o] = SN;
    }
}

// ===========================================================================
// Kernel 3: combine 32 chunk-partials per row -> loss.
// ===========================================================================
__global__ void combine_kernel(float* __restrict__ out) {
    int r = blockIdx.x * blockDim.x + threadIdx.x;
    if (r >= B_ROWS) return;
    float md = -INFINITY, sd = 0.f, mn = -INFINITY, sn = 0.f;
    for (int c = 0; c < NCHUNK; c++) {
        size_t o = (size_t)c * B_ROWS + r;
        float m2 = g_pmd[o], s2 = g_psd[o];
        float M = fmaxf(md, m2);
        sd = sd * __expf(md - M) + s2 * __expf(m2 - M);
        md = M;
        float mn2 = g_pmn[o], sn2 = g_psn[o];
        float Mn = fmaxf(mn, mn2);
        float f0 = (mn == -INFINITY) ? 0.f : __expf(mn - Mn);
        float f1 = (mn2 == -INFINITY) ? 0.f : __expf(mn2 - Mn);
        sn = sn * f0 + sn2 * f1;
        mn = Mn;
    }
    out[r] = (md + logf(sd)) - (mn + logf(sn));
}

// ===========================================================================
// Launch
// ===========================================================================
extern "C" void kernel_launch(void* const* d_in, const int* in_sizes, int n_in,
                              void* d_out, int out_size) {
    const float* feature = (const float*)d_in[0];
    const int* label = (const int*)d_in[1];
    const float* proto = (const float*)d_in[2];
    const int* plab = (const int*)d_in[3];
    float* out = (float*)d_out;

    cudaFuncSetAttribute(dce_mma_kernel, cudaFuncAttributeMaxDynamicSharedMemorySize,
                         SMEM_TOTAL);

    int warps = B_ROWS + P_ROWS;
    prep_kernel<<<(warps * 32 + 255) / 256, 256>>>(feature, proto);

    dim3 grid(P_ROWS / BN, B_ROWS / BM);
    dce_mma_kernel<<<grid, 256, SMEM_TOTAL>>>(label, plab);

    combine_kernel<<<(B_ROWS + 255) / 256, 256>>>(out);
}

// round 10
// speedup vs baseline: 1.1182x; 1.1182x over previous
#include <cuda_runtime.h>
#include <cuda_fp16.h>
#include <math.h>
#include <stdint.h>

// ===========================================================================
// Problem constants
// ===========================================================================
#define B_ROWS 8192
#define P_ROWS 4096
#define D_DIM  512
#define NCHUNK (P_ROWS / 128)     // 32 column chunks of 128 protos

#define BM 128
#define BN 128
#define NTK (D_DIM / 16)           // 32 k16 tiles
#define NTP (P_ROWS / 16)          // 256 n16 (tile-pair) blocks
#define NMT (B_ROWS / 16)          // 512 m16 tiles

#define OFF_PSQ  0                 // 128 floats
#define OFF_PLAB 512               // 128 ints
#define OFF_C    1024
#define CPITCH 132                 // epilogue C smem pitch (floats)
#define EPI_BYTES (128 * CPITCH * 4)                     // 67584
#define SMEM_TOTAL (OFF_C + EPI_BYTES)                   // 68608 -> 2 CTAs/SM

// ===========================================================================
// Scratch (allocation-free)
// A in mma A-fragment order: [mt (512)][tk (32)][lane (32)] x uint4 (a0..a3)
// B in mma B-fragment order: [tk (32)][tp (256)][lane (32)] x uint4
//   uint4 = {tile 2tp: b0, b1, tile 2tp+1: b0, b1}
// ===========================================================================
__device__ uint4 g_Afrag[NMT * NTK * 32];
__device__ uint4 g_Bfrag[NTK * NTP * 32];
__device__ float g_fsq[B_ROWS];
__device__ float g_psq[P_ROWS];
__device__ float g_pmd[NCHUNK * B_ROWS];
__device__ float g_psd[NCHUNK * B_ROWS];
__device__ float g_pmn[NCHUNK * B_ROWS];
__device__ float g_psn[NCHUNK * B_ROWS];

#define MMA16816(c, a, b0, b1)                                                  \
    asm volatile("mma.sync.aligned.m16n8k16.row.col.f32.f16.f16.f32 "           \
        "{%0,%1,%2,%3}, {%4,%5,%6,%7}, {%8,%9}, {%0,%1,%2,%3};"                 \
        : "+f"((c)[0]), "+f"((c)[1]), "+f"((c)[2]), "+f"((c)[3])                \
        : "r"((a).x), "r"((a).y), "r"((a).z), "r"((a).w),                       \
          "r"(b0), "r"(b1))

// ===========================================================================
// Kernel 1: fp16 quantize + squared norms OF THE QUANTIZED vectors, writing
// both operands directly in mma.sync fragment order. One warp per row.
// m16n8k16 A layout: reg = (tr>=8) + 2*(kk>=8); lane = (tr&7)*4 + (kk&7)/2.
// m16n8k16 B layout: reg pair within uint4 by n8-subtile; lane = n'*4+(k'&7)/2.
// ===========================================================================
__global__ void prep_kernel(const float* __restrict__ feat,
                            const float* __restrict__ proto) {
    int warp = (blockIdx.x * blockDim.x + threadIdx.x) >> 5;
    int lane = threadIdx.x & 31;
    if (warp >= B_ROWS + P_ROWS) return;
    bool isA = warp < B_ROWS;
    int row = isA ? warp : warp - B_ROWS;
    const float* src = (isA ? feat : proto) + (size_t)row * D_DIM;

    float s = 0.f;
    if (isA) {
        uint32_t* dst = (uint32_t*)g_Afrag;
        int mt = row >> 4;
        int tr = row & 15;
        int rsel = (tr >> 3) & 1;            // a0/a1 select
        int lane_base = (tr & 7) * 4;
#pragma unroll
        for (int t = 0; t < 8; t++) {
            int k = t * 64 + lane * 2;
            float2 v = *(const float2*)(src + k);
            __half h0 = __float2half_rn(v.x);
            __half h1 = __float2half_rn(v.y);
            float q0 = __half2float(h0), q1 = __half2float(h1);
            s = fmaf(q0, q0, fmaf(q1, q1, s));
            uint32_t pack = (uint32_t)__half_as_ushort(h0)
                          | ((uint32_t)__half_as_ushort(h1) << 16);
            int tk = k >> 4;
            int kk = k & 15;
            int reg = rsel + ((kk >> 3) << 1);
            int lane_t = lane_base + ((kk & 7) >> 1);
            uint32_t idx = (uint32_t)(((mt * NTK + tk) * 32 + lane_t) * 4 + reg);
            dst[idx] = pack;
        }
    } else {
        uint32_t* dst = (uint32_t*)g_Bfrag;
        int pr = row & 7;            // n' within n8 tile
        int tp = row >> 4;           // tile-pair index
        int sub = (row >> 3) & 1;    // which tile of the pair
#pragma unroll
        for (int t = 0; t < 8; t++) {
            int k = t * 64 + lane * 2;
            float2 v = *(const float2*)(src + k);
            __half h0 = __float2half_rn(v.x);
            __half h1 = __float2half_rn(v.y);
            float q0 = __half2float(h0), q1 = __half2float(h1);
            s = fmaf(q0, q0, fmaf(q1, q1, s));
            uint32_t pack = (uint32_t)__half_as_ushort(h0)
                          | ((uint32_t)__half_as_ushort(h1) << 16);
            uint32_t idx = (uint32_t)((((k >> 4) * NTP + tp) * 32
                          + pr * 4 + ((k & 7) >> 1)) * 4
                          + sub * 2 + ((k >> 3) & 1));
            dst[idx] = pack;
        }
    }
#pragma unroll
    for (int m = 16; m; m >>= 1) s += __shfl_xor_sync(0xffffffffu, s, m);
    if (lane == 0) {
        if (isA) g_fsq[row] = s; else g_psq[row] = s;
    }
}

// ===========================================================================
// Kernel 2: pure LDG->mma.sync mainloop (both operands in fragment order,
// L2-resident, register double-buffered). NO smem, NO syncs in mainloop.
// grid = (32 n-chunks, 64 m-tiles), 256 threads = 2(m) x 4(n) warps.
// ===========================================================================
__global__ __launch_bounds__(256, 2) void dce_mma_kernel(
    const int* __restrict__ label, const int* __restrict__ plab) {
    extern __shared__ __align__(1024) char smem[];
    float* psq_s = (float*)(smem + OFF_PSQ);
    int* plab_s = (int*)(smem + OFF_PLAB);

    const int tid = threadIdx.x;
    const int lane = tid & 31;
    const int wid = tid >> 5;
    const int wm = wid >> 2;       // 0..1
    const int wn = wid & 3;        // 0..3
    const int m0 = blockIdx.y * BM;
    const int n0 = blockIdx.x * BN;
    const int mt0 = (m0 >> 4) + wm * 4;    // first of this warp's 4 m16 tiles
    const int tp0 = (n0 >> 4) + wn * 2;    // first of this warp's 2 tile-pairs

    if (tid < 128) {
        psq_s[tid] = g_psq[n0 + tid];
        plab_s[tid] = plab[n0 + tid];
    }

    float acc[4][4][4];
#pragma unroll
    for (int i = 0; i < 4; i++)
#pragma unroll
        for (int j = 0; j < 4; j++)
#pragma unroll
            for (int q = 0; q < 4; q++) acc[i][j][q] = 0.f;

    const uint4* __restrict__ Af = g_Afrag;
    const uint4* __restrict__ Bf = g_Bfrag;

    uint4 a[2][4], b[2][2];
    // preload tk = 0
#pragma unroll
    for (int mt = 0; mt < 4; mt++)
        a[0][mt] = Af[((size_t)(mt0 + mt) * NTK + 0) * 32 + lane];
    b[0][0] = Bf[((size_t)0 * NTP + tp0) * 32 + lane];
    b[0][1] = Bf[((size_t)0 * NTP + tp0 + 1) * 32 + lane];

#pragma unroll 2
    for (int tk = 0; tk < NTK; tk++) {
        int cur = tk & 1, nxt = cur ^ 1;
        if (tk + 1 < NTK) {
#pragma unroll
            for (int mt = 0; mt < 4; mt++)
                a[nxt][mt] = Af[((size_t)(mt0 + mt) * NTK + tk + 1) * 32 + lane];
            b[nxt][0] = Bf[((size_t)(tk + 1) * NTP + tp0) * 32 + lane];
            b[nxt][1] = Bf[((size_t)(tk + 1) * NTP + tp0 + 1) * 32 + lane];
        }
#pragma unroll
        for (int mt = 0; mt < 4; mt++) {
            MMA16816(acc[mt][0], a[cur][mt], b[cur][0].x, b[cur][0].y);
            MMA16816(acc[mt][1], a[cur][mt], b[cur][0].z, b[cur][0].w);
            MMA16816(acc[mt][2], a[cur][mt], b[cur][1].x, b[cur][1].y);
            MMA16816(acc[mt][3], a[cur][mt], b[cur][1].z, b[cur][1].w);
        }
    }

    __syncthreads();   // psq_s/plab_s visible + everyone ready for C dump

    // --- dump accumulators to SMEM ---
    float* Cs = (float*)(smem + OFF_C);
#pragma unroll
    for (int mt = 0; mt < 4; mt++)
#pragma unroll
        for (int nt = 0; nt < 4; nt++) {
            int r = wm * 64 + mt * 16 + (lane >> 2);
            int c = wn * 32 + nt * 8 + ((lane & 3) << 1);
            Cs[r * CPITCH + c] = acc[mt][nt][0];
            Cs[r * CPITCH + c + 1] = acc[mt][nt][1];
            Cs[(r + 8) * CPITCH + c] = acc[mt][nt][2];
            Cs[(r + 8) * CPITCH + c + 1] = acc[mt][nt][3];
        }
    __syncthreads();

    // --- per-thread dual online LSE over 64 cols, pair-merge, write partials
    int row = tid >> 1;
    int c0 = (tid & 1) * 64;
    float fsq = g_fsq[m0 + row];
    int lab = label[m0 + row];
    float md = -INFINITY, mn = -INFINITY;
#pragma unroll 4
    for (int j = 0; j < 64; j++) {
        int col = c0 + j;
        float dot = Cs[row * CPITCH + col];
        float d2 = fmaxf(fsq + psq_s[col] - 2.0f * dot, 0.0f);
        float lg = -d2;
        Cs[row * CPITCH + col] = lg;
        md = fmaxf(md, lg);
        if (plab_s[col] == lab) mn = fmaxf(mn, lg);
    }
    float sd = 0.f, sn = 0.f;
#pragma unroll 4
    for (int j = 0; j < 64; j++) {
        int col = c0 + j;
        float lg = Cs[row * CPITCH + col];
        sd += __expf(lg - md);
        if (plab_s[col] == lab) sn += __expf(lg - mn);
    }
    // merge with partner thread (tid ^ 1, same warp)
    float md2 = __shfl_xor_sync(0xffffffffu, md, 1);
    float sd2 = __shfl_xor_sync(0xffffffffu, sd, 1);
    float mn2 = __shfl_xor_sync(0xffffffffu, mn, 1);
    float sn2 = __shfl_xor_sync(0xffffffffu, sn, 1);
    float M = fmaxf(md, md2);
    float SD = sd * __expf(md - M) + sd2 * __expf(md2 - M);
    float Mn = fmaxf(mn, mn2);
    float f0 = (mn == -INFINITY) ? 0.f : __expf(mn - Mn);
    float f1 = (mn2 == -INFINITY) ? 0.f : __expf(mn2 - Mn);
    float SN = sn * f0 + sn2 * f1;
    if ((tid & 1) == 0) {
        size_t o = (size_t)blockIdx.x * B_ROWS + m0 + row;
        g_pmd[o] = M;
        g_psd[o] = SD;
        g_pmn[o] = Mn;
        g_psn[o] = SN;
    }
}

// ===========================================================================
// Kernel 3: combine 32 chunk-partials per row -> loss.
// ===========================================================================
__global__ void combine_kernel(float* __restrict__ out) {
    int r = blockIdx.x * blockDim.x + threadIdx.x;
    if (r >= B_ROWS) return;
    float md = -INFINITY, sd = 0.f, mn = -INFINITY, sn = 0.f;
    for (int c = 0; c < NCHUNK; c++) {
        size_t o = (size_t)c * B_ROWS + r;
        float m2 = g_pmd[o], s2 = g_psd[o];
        float M = fmaxf(md, m2);
        sd = sd * __expf(md - M) + s2 * __expf(m2 - M);
        md = M;
        float mn2 = g_pmn[o], sn2 = g_psn[o];
        float Mn = fmaxf(mn, mn2);
        float f0 = (mn == -INFINITY) ? 0.f : __expf(mn - Mn);
        float f1 = (mn2 == -INFINITY) ? 0.f : __expf(mn2 - Mn);
        sn = sn * f0 + sn2 * f1;
        mn = Mn;
    }
    out[r] = (md + logf(sd)) - (mn + logf(sn));
}

// ===========================================================================
// Launch
// ===========================================================================
extern "C" void kernel_launch(void* const* d_in, const int* in_sizes, int n_in,
                              void* d_out, int out_size) {
    const float* feature = (const float*)d_in[0];
    const int* label = (const int*)d_in[1];
    const float* proto = (const float*)d_in[2];
    const int* plab = (const int*)d_in[3];
    float* out = (float*)d_out;

    cudaFuncSetAttribute(dce_mma_kernel, cudaFuncAttributeMaxDynamicSharedMemorySize,
                         SMEM_TOTAL);

    int warps = B_ROWS + P_ROWS;
    prep_kernel<<<(warps * 32 + 255) / 256, 256>>>(feature, proto);

    dim3 grid(P_ROWS / BN, B_ROWS / BM);
    dce_mma_kernel<<<grid, 256, SMEM_TOTAL>>>(label, plab);

    combine_kernel<<<(B_ROWS + 255) / 256, 256>>>(out);
}